// round 7
// baseline (speedup 1.0000x reference)
#include <cuda_runtime.h>
#include <math.h>

#define NMAX  12288
#define SEG   1536            // NMAX / NSEG
#define NSEG  8
#define QB    128             // threads per block
#define NB    1036            // persistent blocks: 7/SM x 148 = 1036, guaranteed co-resident
#define EPT   (SEG / QB)      // 12 elements/thread in segment scan
#define SBLK  (NMAX / QB)     // 96 strain blocks
#define TCAP  392             // quarter-segment tile cap: 384 + 8 pad

struct CMat { float m[9]; float s; };

// ---- persistent scratch (zero-init at load; monotone counters, no resets) ----
__device__ float4 g_cand[NMAX];                 // compacted {x,y,z,|w|^2}; padded BIG
__device__ int    g_cidx[NMAX];                 // compact slot -> original index
__device__ int    g_cnt[NSEG];
__device__ unsigned long long g_best[NMAX];     // ~((ord(d)<<32)|slot); 0 = armed
__device__ double g_bsum[SBLK];
__device__ int    g_bcnt[SBLK];
__device__ unsigned int g_c1, g_c2, g_c3;       // monotone barrier/ticket counters

__device__ __forceinline__ unsigned int ford(float f) {
    unsigned int u = __float_as_uint(f);
    return (u & 0x80000000u) ? ~u : (u | 0x80000000u);
}
__device__ __forceinline__ float finv(unsigned int o) {
    unsigned int u = (o & 0x80000000u) ? (o ^ 0x80000000u) : ~o;
    return __uint_as_float(u);
}

// monotone grid barrier (no reset -> no stale-spinner hazard across replays)
__device__ __forceinline__ void gbar(unsigned int* ctr) {
    __syncthreads();
    if (threadIdx.x == 0) {
        __threadfence();
        unsigned int v = atomicAdd(ctr, 1u);
        unsigned int target = (v / NB + 1u) * NB;
        while (*(volatile unsigned int*)ctr < target) __nanosleep(32);
        __threadfence();
    }
    __syncthreads();
}

// ============================================================
// One persistent kernel: compact -> gbar -> NN (batch-min) -> gbar -> strain
// ============================================================
__global__ void __launch_bounds__(QB, 7) k_all(const float* __restrict__ new_xyz,
                                               const float* __restrict__ xyz,
                                               const float* __restrict__ gt_sdf,
                                               CMat C, float* __restrict__ out) {
    __shared__ float4 tile[TCAP];         // 6.3 KB
    __shared__ int    s_w[4];
    __shared__ int    s_pw[NSEG + 1];     // window-count prefix over segments
    __shared__ int    s_cnt[NSEG];
    __shared__ double s_rd[QB];
    __shared__ int    s_ri[QB];
    __shared__ int    s_last;

    int tid = threadIdx.x, lane = tid & 31, wid = tid >> 5;
    int b   = blockIdx.x;

    // ---------------- Phase 0: compaction (blocks 0..7) ----------------
    if (b < NSEG) {
        int s0 = b * SEG;
        const float4* ps = (const float4*)(gt_sdf + s0 + EPT * tid);
        float4 a = ps[0], bb = ps[1], cc = ps[2];
        float v[12] = {a.x,a.y,a.z,a.w, bb.x,bb.y,bb.z,bb.w, cc.x,cc.y,cc.z,cc.w};
        unsigned fl = 0; int myc = 0;
        #pragma unroll
        for (int e = 0; e < 12; ++e) if (v[e] < 1e-8f) { fl |= 1u << e; myc++; }
        int pre = myc;
        #pragma unroll
        for (int o = 1; o < 32; o <<= 1) { int t2 = __shfl_up_sync(~0u, pre, o); if (lane >= o) pre += t2; }
        if (lane == 31) s_w[wid] = pre;
        __syncthreads();
        int woff = 0;
        #pragma unroll
        for (int w = 0; w < 4; ++w) if (w < wid) woff += s_w[w];
        int pos = woff + pre - myc;
        int cnt = s_w[0] + s_w[1] + s_w[2] + s_w[3];
        #pragma unroll
        for (int e = 0; e < 12; ++e) {
            if (fl & (1u << e)) {
                int idx = s0 + EPT * tid + e;
                float x = new_xyz[3 * idx + 0];
                float y = new_xyz[3 * idx + 1];
                float z = new_xyz[3 * idx + 2];
                g_cand[s0 + pos] = make_float4(x, y, z, x * x + y * y + z * z);
                g_cidx[s0 + pos] = idx;
                pos++;
            }
        }
        for (int p = cnt + tid; p < SEG; p += QB)
            g_cand[s0 + p] = make_float4(0.f, 0.f, 0.f, 1e30f);
        if (tid == 0) g_cnt[b] = cnt;
    }

    gbar(&g_c1);

    // ---------------- Phase 1: NN over dynamic work items ----------------
    // item = (active query window) x (candidate segment) x (quarter).
    if (tid < NSEG) s_cnt[tid] = g_cnt[tid];
    __syncthreads();
    if (tid == 0) {
        int acc = 0;
        #pragma unroll
        for (int s = 0; s < NSEG; ++s) {
            s_pw[s] = acc;
            acc += (s_cnt[s] + QB - 1) / QB;
        }
        s_pw[NSEG] = acc;
    }
    __syncthreads();
    int total = s_pw[NSEG] * NSEG * 4;                    // 32 items per window

    for (int it = b; it < total; it += NB) {
        if (it != b) __syncthreads();                     // tile reuse guard
        int widx = it >> 5;                               // / 32
        int r    = it & 31;
        int cs   = r >> 2;
        int qtr  = r & 3;
        int qseg = 0;
        #pragma unroll
        for (int s = 0; s < NSEG - 1; ++s) if (widx >= s_pw[s + 1]) qseg = s + 1;
        int qw0  = (widx - s_pw[qseg]) * QB;
        int cntq = s_cnt[qseg];

        int ql = qw0 + tid;
        bool qa = (ql < cntq);
        float4 wq = g_cand[qseg * SEG + min(ql, SEG - 1)];
        float ax = -2.f * wq.x, ay = -2.f * wq.y, az = -2.f * wq.z;

        int cntseg = s_cnt[cs];
        int base   = cntseg >> 2, rem = cntseg & 3;
        int off    = qtr * base + min(qtr, rem);
        int cntc   = base + (qtr < rem ? 1 : 0);
        bool selfseg = (cs == qseg);                      // block-uniform

        for (int k = tid; k < cntc; k += QB)
            tile[k] = g_cand[cs * SEG + off + k];
        if (tid < 8)                                      // pad for batch-8
            tile[cntc + tid] = make_float4(0.f, 0.f, 0.f, 1e30f);
        __syncthreads();
        if (cntc <= 0) continue;                          // block-uniform

        int cntc8 = (cntc + 7) & ~7;
        float best = 3.0e38f;
        int   kb   = 0;
        int   sk   = ql - off;                            // self slot within quarter

        if (!selfseg) {
            for (int k = 0; k < cntc8; k += 8) {
                float4 c0 = tile[k+0], c1 = tile[k+1], c2 = tile[k+2], c3 = tile[k+3];
                float4 c4 = tile[k+4], c5 = tile[k+5], c6 = tile[k+6], c7 = tile[k+7];
                float d0 = fmaf(c0.x, ax, fmaf(c0.y, ay, fmaf(c0.z, az, c0.w)));
                float d1 = fmaf(c1.x, ax, fmaf(c1.y, ay, fmaf(c1.z, az, c1.w)));
                float d2 = fmaf(c2.x, ax, fmaf(c2.y, ay, fmaf(c2.z, az, c2.w)));
                float d3 = fmaf(c3.x, ax, fmaf(c3.y, ay, fmaf(c3.z, az, c3.w)));
                float d4 = fmaf(c4.x, ax, fmaf(c4.y, ay, fmaf(c4.z, az, c4.w)));
                float d5 = fmaf(c5.x, ax, fmaf(c5.y, ay, fmaf(c5.z, az, c5.w)));
                float d6 = fmaf(c6.x, ax, fmaf(c6.y, ay, fmaf(c6.z, az, c6.w)));
                float d7 = fmaf(c7.x, ax, fmaf(c7.y, ay, fmaf(c7.z, az, c7.w)));
                float m = fminf(fminf(fminf(d0, d1), fminf(d2, d3)),
                                fminf(fminf(d4, d5), fminf(d6, d7)));
                if (m < best) { best = m; kb = k; }       // one pred-update per batch
            }
        } else {
            for (int k = 0; k < cntc8; k += 8) {
                float4 c0 = tile[k+0], c1 = tile[k+1], c2 = tile[k+2], c3 = tile[k+3];
                float4 c4 = tile[k+4], c5 = tile[k+5], c6 = tile[k+6], c7 = tile[k+7];
                float d0 = fmaf(c0.x, ax, fmaf(c0.y, ay, fmaf(c0.z, az, c0.w)));
                float d1 = fmaf(c1.x, ax, fmaf(c1.y, ay, fmaf(c1.z, az, c1.w)));
                float d2 = fmaf(c2.x, ax, fmaf(c2.y, ay, fmaf(c2.z, az, c2.w)));
                float d3 = fmaf(c3.x, ax, fmaf(c3.y, ay, fmaf(c3.z, az, c3.w)));
                float d4 = fmaf(c4.x, ax, fmaf(c4.y, ay, fmaf(c4.z, az, c4.w)));
                float d5 = fmaf(c5.x, ax, fmaf(c5.y, ay, fmaf(c5.z, az, c5.w)));
                float d6 = fmaf(c6.x, ax, fmaf(c6.y, ay, fmaf(c6.z, az, c6.w)));
                float d7 = fmaf(c7.x, ax, fmaf(c7.y, ay, fmaf(c7.z, az, c7.w)));
                if (__any_sync(0xffffffffu, (unsigned)(sk - k) < 8u)) {  // rare fixup
                    d0 = (k + 0 == sk) ? 3e38f : d0;
                    d1 = (k + 1 == sk) ? 3e38f : d1;
                    d2 = (k + 2 == sk) ? 3e38f : d2;
                    d3 = (k + 3 == sk) ? 3e38f : d3;
                    d4 = (k + 4 == sk) ? 3e38f : d4;
                    d5 = (k + 5 == sk) ? 3e38f : d5;
                    d6 = (k + 6 == sk) ? 3e38f : d6;
                    d7 = (k + 7 == sk) ? 3e38f : d7;
                }
                float m = fminf(fminf(fminf(d0, d1), fminf(d2, d3)),
                                fminf(fminf(d4, d5), fminf(d6, d7)));
                if (m < best) { best = m; kb = k; }
            }
        }

        // recovery: first element of winning batch with d == best (bit-identical)
        if (qa) {
            int bi = kb;
            bool found = false;
            #pragma unroll
            for (int i = 0; i < 8; ++i) {
                float4 c = tile[kb + i];
                float d = fmaf(c.x, ax, fmaf(c.y, ay, fmaf(c.z, az, c.w)));
                bool self = selfseg && (kb + i == sk);
                if (!found && !self && d == best) { bi = kb + i; found = true; }
            }
            unsigned long long key =
                ((unsigned long long)ford(best) << 32) | (unsigned int)(cs * SEG + off + bi);
            atomicMax(&g_best[qseg * SEG + ql], ~key);    // keyed by query compact slot
        }
    }

    gbar(&g_c2);

    // ---------------- Phase 2: strain + reduction (blocks 0..95) ----------
    if (b >= SBLK) return;

    // one thread per compact query slot (covers all segments; empty slots give 0)
    int slot = b * QB + tid;
    int qseg2 = slot / SEG;
    int ql2   = slot - qseg2 * SEG;
    double qsq = 0.0;
    int cnt = 0;
    unsigned long long kp = g_best[slot];
    g_best[slot] = 0ULL;                                  // re-arm for next replay
    if (kp != 0ULL && ql2 < g_cnt[qseg2]) {
        unsigned long long key = ~kp;
        float deff = finv((unsigned int)(key >> 32));
        int   nslot = (int)(unsigned int)(key & 0xffffffffu);
        int   i  = g_cidx[slot];
        int   nn = g_cidx[nslot];
        float wqx = new_xyz[3 * i + 0], wqy = new_xyz[3 * i + 1], wqz = new_xyz[3 * i + 2];
        float sqi = wqx * wqx + wqy * wqy + wqz * wqz;
        float mind2 = deff + sqi;
        if (mind2 > 1e-16f) {
            cnt = 1;
            float wnx = new_xyz[3 * nn + 0], wny = new_xyz[3 * nn + 1], wnz = new_xyz[3 * nn + 2];
            float xi0 = xyz[3 * i + 0],  xi1 = xyz[3 * i + 1],  xi2 = xyz[3 * i + 2];
            float xn0 = xyz[3 * nn + 0], xn1 = xyz[3 * nn + 1], xn2 = xyz[3 * nn + 2];
            float du = (wnx - xn0) - (wqx - xi0);
            float dv = (wny - xn1) - (wqy - xi1);
            float dw = (wnz - xn2) - (wqz - xi2);
            float dx = wnx - wqx + 1e-8f;
            float dy = wny - wqy + 1e-8f;
            float dz = wnz - wqz + 1e-8f;
            float e0 = du / dx, e1 = dv / dy, e2 = dw / dz;
            float e3 = (du / dy + dv / dx) * 0.5f;
            float e4 = (du / dz + dw / dx) * 0.5f;
            float e5 = (dw / dy + dv / dz) * 0.5f;
            float r0 = C.m[0] * e0 + C.m[1] * e1 + C.m[2] * e2;
            float r1 = C.m[3] * e0 + C.m[4] * e1 + C.m[5] * e2;
            float r2 = C.m[6] * e0 + C.m[7] * e1 + C.m[8] * e2;
            float q  = e0 * r0 + e1 * r1 + e2 * r2
                     + C.s * (e3 * e3 + e4 * e4 + e5 * e5);
            qsq = (double)q * (double)q;
        }
    }
    s_rd[tid] = qsq;
    s_ri[tid] = cnt;
    __syncthreads();
    #pragma unroll
    for (int o = QB / 2; o > 0; o >>= 1) {
        if (tid < o) { s_rd[tid] += s_rd[tid + o]; s_ri[tid] += s_ri[tid + o]; }
        __syncthreads();
    }
    if (tid == 0) {
        g_bsum[b] = s_rd[0];
        g_bcnt[b] = s_ri[0];
        __threadfence();
        unsigned int v = atomicAdd(&g_c3, 1u);
        s_last = ((v % SBLK) == SBLK - 1);                // monotone ticket
    }
    __syncthreads();

    if (s_last) {
        __threadfence();
        double s = 0.0; int c = 0;
        if (tid < SBLK) { s = g_bsum[tid]; c = g_bcnt[tid]; }
        s_rd[tid] = s; s_ri[tid] = c;
        __syncthreads();
        #pragma unroll
        for (int o = QB / 2; o > 0; o >>= 1) {
            if (tid < o) { s_rd[tid] += s_rd[tid + o]; s_ri[tid] += s_ri[tid + o]; }
            __syncthreads();
        }
        if (tid == 0)
            out[0] = (float)(sqrt(s_rd[0]) / (double)s_ri[0]);
    }
}

// ============================================================
extern "C" void kernel_launch(void* const* d_in, const int* in_sizes, int n_in,
                              void* d_out, int out_size) {
    const float* new_xyz = (const float*)d_in[0];
    const float* xyz     = (const float*)d_in[1];
    const float* gt_sdf  = (const float*)d_in[2];

    CMat C;
    {
        const double EP = 0.21, VP = 0.4;
        double A[3][3] = {{1.0/EP, -VP/EP, -VP/EP},
                          {-VP/EP, 1.0/EP, -VP/EP},
                          {-VP,    -VP,    1.0/EP}};
        double det = A[0][0]*(A[1][1]*A[2][2]-A[1][2]*A[2][1])
                   - A[0][1]*(A[1][0]*A[2][2]-A[1][2]*A[2][0])
                   + A[0][2]*(A[1][0]*A[2][1]-A[1][1]*A[2][0]);
        double inv[3][3];
        inv[0][0] = (A[1][1]*A[2][2]-A[1][2]*A[2][1])/det;
        inv[0][1] = (A[0][2]*A[2][1]-A[0][1]*A[2][2])/det;
        inv[0][2] = (A[0][1]*A[1][2]-A[0][2]*A[1][1])/det;
        inv[1][0] = (A[1][2]*A[2][0]-A[1][0]*A[2][2])/det;
        inv[1][1] = (A[0][0]*A[2][2]-A[0][2]*A[2][0])/det;
        inv[1][2] = (A[0][2]*A[1][0]-A[0][0]*A[1][2])/det;
        inv[2][0] = (A[1][0]*A[2][1]-A[1][1]*A[2][0])/det;
        inv[2][1] = (A[0][1]*A[2][0]-A[0][0]*A[2][1])/det;
        inv[2][2] = (A[0][0]*A[1][1]-A[0][1]*A[1][0])/det;
        for (int i = 0; i < 3; i++)
            for (int j = 0; j < 3; j++)
                C.m[i * 3 + j] = (float)inv[i][j];
        C.s = (float)(EP / (2.0 * (1.0 + VP)));
    }

    k_all<<<NB, QB>>>(new_xyz, xyz, gt_sdf, C, (float*)d_out);
}

// round 8
// speedup vs baseline: 1.2076x; 1.2076x over previous
#include <cuda_runtime.h>
#include <math.h>

#define NMAX  12288
#define SEG   1536            // NMAX / NSEG
#define NSEG  8
#define QB    128             // threads per block
#define NB    768             // persistent blocks: 6/SM x 148 = 888 >= 768, co-resident
#define EPT   (SEG / QB)      // 12 elements/thread in segment scan
#define SBLK  (NMAX / QB)     // 96 strain blocks
#define QW    256             // queries per window (2 per thread)
#define TCAP  (SEG + 4)       // tile cap (worst-case slice) + pad

struct CMat { float m[9]; float s; };

// ---- persistent scratch (zero-init at load; monotone counters, no resets) ----
__device__ float4 g_cand[NMAX];                 // compacted {x,y,z,|w|^2}; padded BIG
__device__ int    g_cidx[NMAX];                 // compact slot -> original index
__device__ int    g_cnt[NSEG];
__device__ unsigned long long g_best[NMAX];     // ~((ord(d)<<32)|slot); 0 = armed
__device__ double g_bsum[SBLK];
__device__ int    g_bcnt[SBLK];
__device__ unsigned int g_c1, g_c2, g_c3;       // monotone barrier/ticket counters

__device__ __forceinline__ unsigned int ford(float f) {
    unsigned int u = __float_as_uint(f);
    return (u & 0x80000000u) ? ~u : (u | 0x80000000u);
}
__device__ __forceinline__ float finv(unsigned int o) {
    unsigned int u = (o & 0x80000000u) ? (o ^ 0x80000000u) : ~o;
    return __uint_as_float(u);
}

// monotone grid barrier (no reset -> no stale-spinner hazard across replays)
__device__ __forceinline__ void gbar(unsigned int* ctr) {
    __syncthreads();
    if (threadIdx.x == 0) {
        __threadfence();
        unsigned int v = atomicAdd(ctr, 1u);
        unsigned int target = (v / NB + 1u) * NB;
        while (*(volatile unsigned int*)ctr < target) __nanosleep(32);
        __threadfence();
    }
    __syncthreads();
}

// ============================================================
// One persistent kernel: compact -> gbar -> NN (2q/thread, batch-4) -> gbar
// -> strain+reduce
// ============================================================
__global__ void __launch_bounds__(QB, 6) k_all(const float* __restrict__ new_xyz,
                                               const float* __restrict__ xyz,
                                               const float* __restrict__ gt_sdf,
                                               CMat C, float* __restrict__ out) {
    __shared__ float4 tile[TCAP];         // 24.6 KB
    __shared__ int    s_w[4];
    __shared__ int    s_pw[NSEG + 1];     // 256-query window prefix over segments
    __shared__ int    s_cnt[NSEG];
    __shared__ double s_rd[QB];
    __shared__ int    s_ri[QB];
    __shared__ int    s_last;

    int tid = threadIdx.x, lane = tid & 31, wid = tid >> 5;
    int b   = blockIdx.x;

    // ---------------- Phase 0: compaction (blocks 0..7) ----------------
    if (b < NSEG) {
        int s0 = b * SEG;
        const float4* ps = (const float4*)(gt_sdf + s0 + EPT * tid);
        float4 a = ps[0], bb = ps[1], cc = ps[2];
        float v[12] = {a.x,a.y,a.z,a.w, bb.x,bb.y,bb.z,bb.w, cc.x,cc.y,cc.z,cc.w};
        unsigned fl = 0; int myc = 0;
        #pragma unroll
        for (int e = 0; e < 12; ++e) if (v[e] < 1e-8f) { fl |= 1u << e; myc++; }
        int pre = myc;
        #pragma unroll
        for (int o = 1; o < 32; o <<= 1) { int t2 = __shfl_up_sync(~0u, pre, o); if (lane >= o) pre += t2; }
        if (lane == 31) s_w[wid] = pre;
        __syncthreads();
        int woff = 0;
        #pragma unroll
        for (int w = 0; w < 4; ++w) if (w < wid) woff += s_w[w];
        int pos = woff + pre - myc;
        int cnt = s_w[0] + s_w[1] + s_w[2] + s_w[3];
        #pragma unroll
        for (int e = 0; e < 12; ++e) {
            if (fl & (1u << e)) {
                int idx = s0 + EPT * tid + e;
                float x = new_xyz[3 * idx + 0];
                float y = new_xyz[3 * idx + 1];
                float z = new_xyz[3 * idx + 2];
                g_cand[s0 + pos] = make_float4(x, y, z, x * x + y * y + z * z);
                g_cidx[s0 + pos] = idx;
                pos++;
            }
        }
        for (int p = cnt + tid; p < SEG; p += QB)
            g_cand[s0 + p] = make_float4(0.f, 0.f, 0.f, 1e30f);
        if (tid == 0) g_cnt[b] = cnt;
    }

    gbar(&g_c1);

    // ---------------- Phase 1: NN, one uniform item per block ----------------
    if (tid < NSEG) s_cnt[tid] = g_cnt[tid];
    __syncthreads();
    if (tid == 0) {
        int acc = 0;
        #pragma unroll
        for (int s = 0; s < NSEG; ++s) {
            s_pw[s] = acc;
            acc += (s_cnt[s] + QW - 1) / QW;              // 256-query windows
        }
        s_pw[NSEG] = acc;
    }
    __syncthreads();
    int w8   = s_pw[NSEG] * NSEG;                         // (window, cand-seg) pairs
    int S    = NB / w8;                                   // slices per pair (>=1)
    int used = w8 * S;

    if (b < used) {
        int wi    = b % w8;
        int slice = b / w8;
        int widx  = wi >> 3;                              // window index
        int cs    = wi & 7;                               // candidate segment
        int qseg  = 0;
        #pragma unroll
        for (int s = 0; s < NSEG - 1; ++s) if (widx >= s_pw[s + 1]) qseg = s + 1;
        int qw0  = (widx - s_pw[qseg]) * QW;
        int cntq = s_cnt[qseg];

        int cntseg = s_cnt[cs];
        int lo   = (int)((long long)slice * cntseg / S);
        int hi   = (int)((long long)(slice + 1) * cntseg / S);
        int cntc = hi - lo;
        bool selfseg = (cs == qseg);                      // block-uniform

        for (int k = tid; k < cntc; k += QB)
            tile[k] = g_cand[cs * SEG + lo + k];
        if (tid < 4)                                      // pad for batch-4
            tile[cntc + tid] = make_float4(0.f, 0.f, 0.f, 1e30f);
        __syncthreads();

        if (cntc > 0) {                                   // block-uniform
            // two queries per thread
            int ql0 = qw0 + tid, ql1 = qw0 + QB + tid;
            bool qa0 = (ql0 < cntq), qa1 = (ql1 < cntq);
            float4 w0 = g_cand[qseg * SEG + min(ql0, SEG - 1)];
            float4 w1 = g_cand[qseg * SEG + min(ql1, SEG - 1)];
            float ax0 = -2.f * w0.x, ay0 = -2.f * w0.y, az0 = -2.f * w0.z;
            float ax1 = -2.f * w1.x, ay1 = -2.f * w1.y, az1 = -2.f * w1.z;
            int sk0 = ql0 - lo, sk1 = ql1 - lo;           // self slots (self seg only)

            int cntc4 = (cntc + 3) & ~3;
            float best0 = 3.0e38f, best1 = 3.0e38f;
            int   kb0 = 0, kb1 = 0;

            if (!selfseg) {
                for (int k = 0; k < cntc4; k += 4) {
                    float4 c0 = tile[k+0], c1 = tile[k+1], c2 = tile[k+2], c3 = tile[k+3];
                    float dA0 = fmaf(c0.x, ax0, fmaf(c0.y, ay0, fmaf(c0.z, az0, c0.w)));
                    float dA1 = fmaf(c1.x, ax0, fmaf(c1.y, ay0, fmaf(c1.z, az0, c1.w)));
                    float dA2 = fmaf(c2.x, ax0, fmaf(c2.y, ay0, fmaf(c2.z, az0, c2.w)));
                    float dA3 = fmaf(c3.x, ax0, fmaf(c3.y, ay0, fmaf(c3.z, az0, c3.w)));
                    float dB0 = fmaf(c0.x, ax1, fmaf(c0.y, ay1, fmaf(c0.z, az1, c0.w)));
                    float dB1 = fmaf(c1.x, ax1, fmaf(c1.y, ay1, fmaf(c1.z, az1, c1.w)));
                    float dB2 = fmaf(c2.x, ax1, fmaf(c2.y, ay1, fmaf(c2.z, az1, c2.w)));
                    float dB3 = fmaf(c3.x, ax1, fmaf(c3.y, ay1, fmaf(c3.z, az1, c3.w)));
                    float mA = fminf(fminf(dA0, dA1), fminf(dA2, dA3));
                    float mB = fminf(fminf(dB0, dB1), fminf(dB2, dB3));
                    if (mA < best0) { best0 = mA; kb0 = k; }
                    if (mB < best1) { best1 = mB; kb1 = k; }
                }
            } else {
                for (int k = 0; k < cntc4; k += 4) {
                    float4 c0 = tile[k+0], c1 = tile[k+1], c2 = tile[k+2], c3 = tile[k+3];
                    float dA0 = fmaf(c0.x, ax0, fmaf(c0.y, ay0, fmaf(c0.z, az0, c0.w)));
                    float dA1 = fmaf(c1.x, ax0, fmaf(c1.y, ay0, fmaf(c1.z, az0, c1.w)));
                    float dA2 = fmaf(c2.x, ax0, fmaf(c2.y, ay0, fmaf(c2.z, az0, c2.w)));
                    float dA3 = fmaf(c3.x, ax0, fmaf(c3.y, ay0, fmaf(c3.z, az0, c3.w)));
                    float dB0 = fmaf(c0.x, ax1, fmaf(c0.y, ay1, fmaf(c0.z, az1, c0.w)));
                    float dB1 = fmaf(c1.x, ax1, fmaf(c1.y, ay1, fmaf(c1.z, az1, c1.w)));
                    float dB2 = fmaf(c2.x, ax1, fmaf(c2.y, ay1, fmaf(c2.z, az1, c2.w)));
                    float dB3 = fmaf(c3.x, ax1, fmaf(c3.y, ay1, fmaf(c3.z, az1, c3.w)));
                    if (__any_sync(0xffffffffu, ((unsigned)(sk0 - k) < 4u) |
                                                ((unsigned)(sk1 - k) < 4u))) {  // rare
                        dA0 = (k + 0 == sk0) ? 3e38f : dA0;
                        dA1 = (k + 1 == sk0) ? 3e38f : dA1;
                        dA2 = (k + 2 == sk0) ? 3e38f : dA2;
                        dA3 = (k + 3 == sk0) ? 3e38f : dA3;
                        dB0 = (k + 0 == sk1) ? 3e38f : dB0;
                        dB1 = (k + 1 == sk1) ? 3e38f : dB1;
                        dB2 = (k + 2 == sk1) ? 3e38f : dB2;
                        dB3 = (k + 3 == sk1) ? 3e38f : dB3;
                    }
                    float mA = fminf(fminf(dA0, dA1), fminf(dA2, dA3));
                    float mB = fminf(fminf(dB0, dB1), fminf(dB2, dB3));
                    if (mA < best0) { best0 = mA; kb0 = k; }
                    if (mB < best1) { best1 = mB; kb1 = k; }
                }
            }

            // recovery: first element of winning batch with d == best (bit-identical)
            if (qa0) {
                int bi = kb0; bool found = false;
                #pragma unroll
                for (int i = 0; i < 4; ++i) {
                    float4 c = tile[kb0 + i];
                    float d = fmaf(c.x, ax0, fmaf(c.y, ay0, fmaf(c.z, az0, c.w)));
                    bool self = selfseg && (kb0 + i == sk0);
                    if (!found && !self && d == best0) { bi = kb0 + i; found = true; }
                }
                unsigned long long key =
                    ((unsigned long long)ford(best0) << 32) | (unsigned int)(cs * SEG + lo + bi);
                atomicMax(&g_best[qseg * SEG + ql0], ~key);
            }
            if (qa1) {
                int bi = kb1; bool found = false;
                #pragma unroll
                for (int i = 0; i < 4; ++i) {
                    float4 c = tile[kb1 + i];
                    float d = fmaf(c.x, ax1, fmaf(c.y, ay1, fmaf(c.z, az1, c.w)));
                    bool self = selfseg && (kb1 + i == sk1);
                    if (!found && !self && d == best1) { bi = kb1 + i; found = true; }
                }
                unsigned long long key =
                    ((unsigned long long)ford(best1) << 32) | (unsigned int)(cs * SEG + lo + bi);
                atomicMax(&g_best[qseg * SEG + ql1], ~key);
            }
        }
    }

    gbar(&g_c2);

    // ---------------- Phase 2: strain + reduction (blocks 0..95) ----------
    if (b >= SBLK) return;

    int slot = b * QB + tid;                              // compact query slot
    int qseg2 = slot / SEG;
    int ql2   = slot - qseg2 * SEG;
    double qsq = 0.0;
    int cnt = 0;
    unsigned long long kp = g_best[slot];
    g_best[slot] = 0ULL;                                  // re-arm for next replay
    if (kp != 0ULL && ql2 < g_cnt[qseg2]) {
        unsigned long long key = ~kp;
        float deff = finv((unsigned int)(key >> 32));
        int   nslot = (int)(unsigned int)(key & 0xffffffffu);
        int   i  = g_cidx[slot];
        int   nn = g_cidx[nslot];
        float wqx = new_xyz[3 * i + 0], wqy = new_xyz[3 * i + 1], wqz = new_xyz[3 * i + 2];
        float sqi = wqx * wqx + wqy * wqy + wqz * wqz;
        float mind2 = deff + sqi;
        if (mind2 > 1e-16f) {
            cnt = 1;
            float wnx = new_xyz[3 * nn + 0], wny = new_xyz[3 * nn + 1], wnz = new_xyz[3 * nn + 2];
            float xi0 = xyz[3 * i + 0],  xi1 = xyz[3 * i + 1],  xi2 = xyz[3 * i + 2];
            float xn0 = xyz[3 * nn + 0], xn1 = xyz[3 * nn + 1], xn2 = xyz[3 * nn + 2];
            float du = (wnx - xn0) - (wqx - xi0);
            float dv = (wny - xn1) - (wqy - xi1);
            float dw = (wnz - xn2) - (wqz - xi2);
            float dx = wnx - wqx + 1e-8f;
            float dy = wny - wqy + 1e-8f;
            float dz = wnz - wqz + 1e-8f;
            float e0 = du / dx, e1 = dv / dy, e2 = dw / dz;
            float e3 = (du / dy + dv / dx) * 0.5f;
            float e4 = (du / dz + dw / dx) * 0.5f;
            float e5 = (dw / dy + dv / dz) * 0.5f;
            float r0 = C.m[0] * e0 + C.m[1] * e1 + C.m[2] * e2;
            float r1 = C.m[3] * e0 + C.m[4] * e1 + C.m[5] * e2;
            float r2 = C.m[6] * e0 + C.m[7] * e1 + C.m[8] * e2;
            float q  = e0 * r0 + e1 * r1 + e2 * r2
                     + C.s * (e3 * e3 + e4 * e4 + e5 * e5);
            qsq = (double)q * (double)q;
        }
    }
    s_rd[tid] = qsq;
    s_ri[tid] = cnt;
    __syncthreads();
    #pragma unroll
    for (int o = QB / 2; o > 0; o >>= 1) {
        if (tid < o) { s_rd[tid] += s_rd[tid + o]; s_ri[tid] += s_ri[tid + o]; }
        __syncthreads();
    }
    if (tid == 0) {
        g_bsum[b] = s_rd[0];
        g_bcnt[b] = s_ri[0];
        __threadfence();
        unsigned int v = atomicAdd(&g_c3, 1u);
        s_last = ((v % SBLK) == SBLK - 1);                // monotone ticket
    }
    __syncthreads();

    if (s_last) {
        __threadfence();
        double s = 0.0; int c = 0;
        if (tid < SBLK) { s = g_bsum[tid]; c = g_bcnt[tid]; }
        s_rd[tid] = s; s_ri[tid] = c;
        __syncthreads();
        #pragma unroll
        for (int o = QB / 2; o > 0; o >>= 1) {
            if (tid < o) { s_rd[tid] += s_rd[tid + o]; s_ri[tid] += s_ri[tid + o]; }
            __syncthreads();
        }
        if (tid == 0)
            out[0] = (float)(sqrt(s_rd[0]) / (double)s_ri[0]);
    }
}

// ============================================================
extern "C" void kernel_launch(void* const* d_in, const int* in_sizes, int n_in,
                              void* d_out, int out_size) {
    const float* new_xyz = (const float*)d_in[0];
    const float* xyz     = (const float*)d_in[1];
    const float* gt_sdf  = (const float*)d_in[2];

    CMat C;
    {
        const double EP = 0.21, VP = 0.4;
        double A[3][3] = {{1.0/EP, -VP/EP, -VP/EP},
                          {-VP/EP, 1.0/EP, -VP/EP},
                          {-VP,    -VP,    1.0/EP}};
        double det = A[0][0]*(A[1][1]*A[2][2]-A[1][2]*A[2][1])
                   - A[0][1]*(A[1][0]*A[2][2]-A[1][2]*A[2][0])
                   + A[0][2]*(A[1][0]*A[2][1]-A[1][1]*A[2][0]);
        double inv[3][3];
        inv[0][0] = (A[1][1]*A[2][2]-A[1][2]*A[2][1])/det;
        inv[0][1] = (A[0][2]*A[2][1]-A[0][1]*A[2][2])/det;
        inv[0][2] = (A[0][1]*A[1][2]-A[0][2]*A[1][1])/det;
        inv[1][0] = (A[1][2]*A[2][0]-A[1][0]*A[2][2])/det;
        inv[1][1] = (A[0][0]*A[2][2]-A[0][2]*A[2][0])/det;
        inv[1][2] = (A[0][2]*A[1][0]-A[0][0]*A[1][2])/det;
        inv[2][0] = (A[1][0]*A[2][1]-A[1][1]*A[2][0])/det;
        inv[2][1] = (A[0][1]*A[2][0]-A[0][0]*A[2][1])/det;
        inv[2][2] = (A[0][0]*A[1][1]-A[0][1]*A[1][0])/det;
        for (int i = 0; i < 3; i++)
            for (int j = 0; j < 3; j++)
                C.m[i * 3 + j] = (float)inv[i][j];
        C.s = (float)(EP / (2.0 * (1.0 + VP)));
    }

    k_all<<<NB, QB>>>(new_xyz, xyz, gt_sdf, C, (float*)d_out);
}

// round 9
// speedup vs baseline: 1.2182x; 1.0088x over previous
#include <cuda_runtime.h>
#include <math.h>

#define NMAX  12288
#define SEG   1536            // NMAX / NSEG
#define NSEG  8
#define QB    128             // threads per block
#define NB    768             // persistent blocks: 6/SM x 148 = 888 >= 768, co-resident
#define EPT   (SEG / QB)      // 12 elements/thread in segment scan
#define SBLK  (NMAX / QB)     // 96 strain blocks
#define QW    256             // queries per window (2 per thread)
#define TCAP  (SEG + 4)       // tile cap (worst-case slice) + pad

struct CMat { float m[9]; float s; };

// ---- persistent scratch (zero-init at load; monotone counters, no resets) ----
__device__ float4 g_cand[NMAX];                 // compacted {x,y,z,|w|^2}; padded BIG
__device__ int    g_cidx[NMAX];                 // compact slot -> original index
__device__ int    g_cnt[NSEG];
__device__ unsigned long long g_best[NMAX];     // ~((ord(d)<<32)|slot); 0 = armed
__device__ double g_bsum[SBLK];
__device__ int    g_bcnt[SBLK];
__device__ unsigned int g_c1, g_c2, g_c3;       // monotone barrier/ticket counters

__device__ __forceinline__ unsigned int ford(float f) {
    unsigned int u = __float_as_uint(f);
    return (u & 0x80000000u) ? ~u : (u | 0x80000000u);
}
__device__ __forceinline__ float finv(unsigned int o) {
    unsigned int u = (o & 0x80000000u) ? (o ^ 0x80000000u) : ~o;
    return __uint_as_float(u);
}

// monotone grid barrier (no reset -> no stale-spinner hazard across replays)
__device__ __forceinline__ void gbar(unsigned int* ctr) {
    __syncthreads();
    if (threadIdx.x == 0) {
        __threadfence();
        unsigned int v = atomicAdd(ctr, 1u);
        unsigned int target = (v / NB + 1u) * NB;
        while (*(volatile unsigned int*)ctr < target) __nanosleep(32);
        __threadfence();
    }
    __syncthreads();
}

// ============================================================
// One persistent kernel: compact -> gbar -> NN (2q/thread, batch-4) -> gbar
// -> strain+reduce
// ============================================================
__global__ void __launch_bounds__(QB, 6) k_all(const float* __restrict__ new_xyz,
                                               const float* __restrict__ xyz,
                                               const float* __restrict__ gt_sdf,
                                               CMat C, float* __restrict__ out) {
    __shared__ float4 tile[TCAP];         // 24.6 KB
    __shared__ int    s_w[4];
    __shared__ int    s_pw[NSEG + 1];     // 256-query window prefix over segments
    __shared__ int    s_cnt[NSEG];
    __shared__ double s_rd[QB];
    __shared__ int    s_ri[QB];
    __shared__ int    s_last;

    int tid = threadIdx.x, lane = tid & 31, wid = tid >> 5;
    int b   = blockIdx.x;

    // ---------------- Phase 0: compaction (blocks 0..7) ----------------
    if (b < NSEG) {
        int s0 = b * SEG;
        const float4* ps = (const float4*)(gt_sdf + s0 + EPT * tid);
        float4 a = ps[0], bb = ps[1], cc = ps[2];
        float v[12] = {a.x,a.y,a.z,a.w, bb.x,bb.y,bb.z,bb.w, cc.x,cc.y,cc.z,cc.w};
        unsigned fl = 0; int myc = 0;
        #pragma unroll
        for (int e = 0; e < 12; ++e) if (v[e] < 1e-8f) { fl |= 1u << e; myc++; }
        int pre = myc;
        #pragma unroll
        for (int o = 1; o < 32; o <<= 1) { int t2 = __shfl_up_sync(~0u, pre, o); if (lane >= o) pre += t2; }
        if (lane == 31) s_w[wid] = pre;
        __syncthreads();
        int woff = 0;
        #pragma unroll
        for (int w = 0; w < 4; ++w) if (w < wid) woff += s_w[w];
        int pos = woff + pre - myc;
        int cnt = s_w[0] + s_w[1] + s_w[2] + s_w[3];
        #pragma unroll
        for (int e = 0; e < 12; ++e) {
            if (fl & (1u << e)) {
                int idx = s0 + EPT * tid + e;
                float x = new_xyz[3 * idx + 0];
                float y = new_xyz[3 * idx + 1];
                float z = new_xyz[3 * idx + 2];
                g_cand[s0 + pos] = make_float4(x, y, z, x * x + y * y + z * z);
                g_cidx[s0 + pos] = idx;
                pos++;
            }
        }
        for (int p = cnt + tid; p < SEG; p += QB)
            g_cand[s0 + p] = make_float4(0.f, 0.f, 0.f, 1e30f);
        if (tid == 0) g_cnt[b] = cnt;
    }

    gbar(&g_c1);

    // ---------------- Phase 1: NN, one uniform item per block ----------------
    if (tid < NSEG) s_cnt[tid] = g_cnt[tid];
    __syncthreads();
    if (tid == 0) {
        int acc = 0;
        #pragma unroll
        for (int s = 0; s < NSEG; ++s) {
            s_pw[s] = acc;
            acc += (s_cnt[s] + QW - 1) / QW;              // 256-query windows
        }
        s_pw[NSEG] = acc;
    }
    __syncthreads();
    int w8   = s_pw[NSEG] * NSEG;                         // (window, cand-seg) pairs
    int S    = NB / w8;                                   // slices per pair (>=1)
    int used = w8 * S;

    if (b < used) {
        int wi    = b % w8;
        int slice = b / w8;
        int widx  = wi >> 3;                              // window index
        int cs    = wi & 7;                               // candidate segment
        int qseg  = 0;
        #pragma unroll
        for (int s = 0; s < NSEG - 1; ++s) if (widx >= s_pw[s + 1]) qseg = s + 1;
        int qw0  = (widx - s_pw[qseg]) * QW;
        int cntq = s_cnt[qseg];

        int cntseg = s_cnt[cs];
        int lo   = (int)((long long)slice * cntseg / S);
        int hi   = (int)((long long)(slice + 1) * cntseg / S);
        int cntc = hi - lo;
        bool selfseg = (cs == qseg);                      // block-uniform

        for (int k = tid; k < cntc; k += QB)
            tile[k] = g_cand[cs * SEG + lo + k];
        if (tid < 4)                                      // pad for batch-4
            tile[cntc + tid] = make_float4(0.f, 0.f, 0.f, 1e30f);
        __syncthreads();

        if (cntc > 0) {                                   // block-uniform
            // two queries per thread
            int ql0 = qw0 + tid, ql1 = qw0 + QB + tid;
            bool qa0 = (ql0 < cntq), qa1 = (ql1 < cntq);
            float4 w0 = g_cand[qseg * SEG + min(ql0, SEG - 1)];
            float4 w1 = g_cand[qseg * SEG + min(ql1, SEG - 1)];
            float ax0 = -2.f * w0.x, ay0 = -2.f * w0.y, az0 = -2.f * w0.z;
            float ax1 = -2.f * w1.x, ay1 = -2.f * w1.y, az1 = -2.f * w1.z;
            int sk0 = ql0 - lo, sk1 = ql1 - lo;           // self slots (self seg only)

            int cntc4 = (cntc + 3) & ~3;
            float best0 = 3.0e38f, best1 = 3.0e38f;
            int   kb0 = 0, kb1 = 0;

            if (!selfseg) {
                for (int k = 0; k < cntc4; k += 4) {
                    float4 c0 = tile[k+0], c1 = tile[k+1], c2 = tile[k+2], c3 = tile[k+3];
                    float dA0 = fmaf(c0.x, ax0, fmaf(c0.y, ay0, fmaf(c0.z, az0, c0.w)));
                    float dA1 = fmaf(c1.x, ax0, fmaf(c1.y, ay0, fmaf(c1.z, az0, c1.w)));
                    float dA2 = fmaf(c2.x, ax0, fmaf(c2.y, ay0, fmaf(c2.z, az0, c2.w)));
                    float dA3 = fmaf(c3.x, ax0, fmaf(c3.y, ay0, fmaf(c3.z, az0, c3.w)));
                    float dB0 = fmaf(c0.x, ax1, fmaf(c0.y, ay1, fmaf(c0.z, az1, c0.w)));
                    float dB1 = fmaf(c1.x, ax1, fmaf(c1.y, ay1, fmaf(c1.z, az1, c1.w)));
                    float dB2 = fmaf(c2.x, ax1, fmaf(c2.y, ay1, fmaf(c2.z, az1, c2.w)));
                    float dB3 = fmaf(c3.x, ax1, fmaf(c3.y, ay1, fmaf(c3.z, az1, c3.w)));
                    float mA = fminf(fminf(dA0, dA1), fminf(dA2, dA3));
                    float mB = fminf(fminf(dB0, dB1), fminf(dB2, dB3));
                    if (mA < best0) { best0 = mA; kb0 = k; }
                    if (mB < best1) { best1 = mB; kb1 = k; }
                }
            } else {
                for (int k = 0; k < cntc4; k += 4) {
                    float4 c0 = tile[k+0], c1 = tile[k+1], c2 = tile[k+2], c3 = tile[k+3];
                    float dA0 = fmaf(c0.x, ax0, fmaf(c0.y, ay0, fmaf(c0.z, az0, c0.w)));
                    float dA1 = fmaf(c1.x, ax0, fmaf(c1.y, ay0, fmaf(c1.z, az0, c1.w)));
                    float dA2 = fmaf(c2.x, ax0, fmaf(c2.y, ay0, fmaf(c2.z, az0, c2.w)));
                    float dA3 = fmaf(c3.x, ax0, fmaf(c3.y, ay0, fmaf(c3.z, az0, c3.w)));
                    float dB0 = fmaf(c0.x, ax1, fmaf(c0.y, ay1, fmaf(c0.z, az1, c0.w)));
                    float dB1 = fmaf(c1.x, ax1, fmaf(c1.y, ay1, fmaf(c1.z, az1, c1.w)));
                    float dB2 = fmaf(c2.x, ax1, fmaf(c2.y, ay1, fmaf(c2.z, az1, c2.w)));
                    float dB3 = fmaf(c3.x, ax1, fmaf(c3.y, ay1, fmaf(c3.z, az1, c3.w)));
                    if (__any_sync(0xffffffffu, ((unsigned)(sk0 - k) < 4u) |
                                                ((unsigned)(sk1 - k) < 4u))) {  // rare
                        dA0 = (k + 0 == sk0) ? 3e38f : dA0;
                        dA1 = (k + 1 == sk0) ? 3e38f : dA1;
                        dA2 = (k + 2 == sk0) ? 3e38f : dA2;
                        dA3 = (k + 3 == sk0) ? 3e38f : dA3;
                        dB0 = (k + 0 == sk1) ? 3e38f : dB0;
                        dB1 = (k + 1 == sk1) ? 3e38f : dB1;
                        dB2 = (k + 2 == sk1) ? 3e38f : dB2;
                        dB3 = (k + 3 == sk1) ? 3e38f : dB3;
                    }
                    float mA = fminf(fminf(dA0, dA1), fminf(dA2, dA3));
                    float mB = fminf(fminf(dB0, dB1), fminf(dB2, dB3));
                    if (mA < best0) { best0 = mA; kb0 = k; }
                    if (mB < best1) { best1 = mB; kb1 = k; }
                }
            }

            // recovery: first element of winning batch with d == best (bit-identical)
            if (qa0) {
                int bi = kb0; bool found = false;
                #pragma unroll
                for (int i = 0; i < 4; ++i) {
                    float4 c = tile[kb0 + i];
                    float d = fmaf(c.x, ax0, fmaf(c.y, ay0, fmaf(c.z, az0, c.w)));
                    bool self = selfseg && (kb0 + i == sk0);
                    if (!found && !self && d == best0) { bi = kb0 + i; found = true; }
                }
                unsigned long long key =
                    ((unsigned long long)ford(best0) << 32) | (unsigned int)(cs * SEG + lo + bi);
                atomicMax(&g_best[qseg * SEG + ql0], ~key);
            }
            if (qa1) {
                int bi = kb1; bool found = false;
                #pragma unroll
                for (int i = 0; i < 4; ++i) {
                    float4 c = tile[kb1 + i];
                    float d = fmaf(c.x, ax1, fmaf(c.y, ay1, fmaf(c.z, az1, c.w)));
                    bool self = selfseg && (kb1 + i == sk1);
                    if (!found && !self && d == best1) { bi = kb1 + i; found = true; }
                }
                unsigned long long key =
                    ((unsigned long long)ford(best1) << 32) | (unsigned int)(cs * SEG + lo + bi);
                atomicMax(&g_best[qseg * SEG + ql1], ~key);
            }
        }
    }

    gbar(&g_c2);

    // ---------------- Phase 2: strain + reduction (blocks 0..95) ----------
    if (b >= SBLK) return;

    int slot = b * QB + tid;                              // compact query slot
    int qseg2 = slot / SEG;
    int ql2   = slot - qseg2 * SEG;
    double qsq = 0.0;
    int cnt = 0;
    unsigned long long kp = g_best[slot];
    g_best[slot] = 0ULL;                                  // re-arm for next replay
    if (kp != 0ULL && ql2 < g_cnt[qseg2]) {
        unsigned long long key = ~kp;
        float deff = finv((unsigned int)(key >> 32));
        int   nslot = (int)(unsigned int)(key & 0xffffffffu);
        int   i  = g_cidx[slot];
        int   nn = g_cidx[nslot];
        float wqx = new_xyz[3 * i + 0], wqy = new_xyz[3 * i + 1], wqz = new_xyz[3 * i + 2];
        float sqi = wqx * wqx + wqy * wqy + wqz * wqz;
        float mind2 = deff + sqi;
        if (mind2 > 1e-16f) {
            cnt = 1;
            float wnx = new_xyz[3 * nn + 0], wny = new_xyz[3 * nn + 1], wnz = new_xyz[3 * nn + 2];
            float xi0 = xyz[3 * i + 0],  xi1 = xyz[3 * i + 1],  xi2 = xyz[3 * i + 2];
            float xn0 = xyz[3 * nn + 0], xn1 = xyz[3 * nn + 1], xn2 = xyz[3 * nn + 2];
            float du = (wnx - xn0) - (wqx - xi0);
            float dv = (wny - xn1) - (wqy - xi1);
            float dw = (wnz - xn2) - (wqz - xi2);
            float dx = wnx - wqx + 1e-8f;
            float dy = wny - wqy + 1e-8f;
            float dz = wnz - wqz + 1e-8f;
            float e0 = du / dx, e1 = dv / dy, e2 = dw / dz;
            float e3 = (du / dy + dv / dx) * 0.5f;
            float e4 = (du / dz + dw / dx) * 0.5f;
            float e5 = (dw / dy + dv / dz) * 0.5f;
            float r0 = C.m[0] * e0 + C.m[1] * e1 + C.m[2] * e2;
            float r1 = C.m[3] * e0 + C.m[4] * e1 + C.m[5] * e2;
            float r2 = C.m[6] * e0 + C.m[7] * e1 + C.m[8] * e2;
            float q  = e0 * r0 + e1 * r1 + e2 * r2
                     + C.s * (e3 * e3 + e4 * e4 + e5 * e5);
            qsq = (double)q * (double)q;
        }
    }
    s_rd[tid] = qsq;
    s_ri[tid] = cnt;
    __syncthreads();
    #pragma unroll
    for (int o = QB / 2; o > 0; o >>= 1) {
        if (tid < o) { s_rd[tid] += s_rd[tid + o]; s_ri[tid] += s_ri[tid + o]; }
        __syncthreads();
    }
    if (tid == 0) {
        g_bsum[b] = s_rd[0];
        g_bcnt[b] = s_ri[0];
        __threadfence();
        unsigned int v = atomicAdd(&g_c3, 1u);
        s_last = ((v % SBLK) == SBLK - 1);                // monotone ticket
    }
    __syncthreads();

    if (s_last) {
        __threadfence();
        double s = 0.0; int c = 0;
        if (tid < SBLK) { s = g_bsum[tid]; c = g_bcnt[tid]; }
        s_rd[tid] = s; s_ri[tid] = c;
        __syncthreads();
        #pragma unroll
        for (int o = QB / 2; o > 0; o >>= 1) {
            if (tid < o) { s_rd[tid] += s_rd[tid + o]; s_ri[tid] += s_ri[tid + o]; }
            __syncthreads();
        }
        if (tid == 0)
            out[0] = (float)(sqrt(s_rd[0]) / (double)s_ri[0]);
    }
}

// ============================================================
extern "C" void kernel_launch(void* const* d_in, const int* in_sizes, int n_in,
                              void* d_out, int out_size) {
    const float* new_xyz = (const float*)d_in[0];
    const float* xyz     = (const float*)d_in[1];
    const float* gt_sdf  = (const float*)d_in[2];

    CMat C;
    {
        const double EP = 0.21, VP = 0.4;
        double A[3][3] = {{1.0/EP, -VP/EP, -VP/EP},
                          {-VP/EP, 1.0/EP, -VP/EP},
                          {-VP,    -VP,    1.0/EP}};
        double det = A[0][0]*(A[1][1]*A[2][2]-A[1][2]*A[2][1])
                   - A[0][1]*(A[1][0]*A[2][2]-A[1][2]*A[2][0])
                   + A[0][2]*(A[1][0]*A[2][1]-A[1][1]*A[2][0]);
        double inv[3][3];
        inv[0][0] = (A[1][1]*A[2][2]-A[1][2]*A[2][1])/det;
        inv[0][1] = (A[0][2]*A[2][1]-A[0][1]*A[2][2])/det;
        inv[0][2] = (A[0][1]*A[1][2]-A[0][2]*A[1][1])/det;
        inv[1][0] = (A[1][2]*A[2][0]-A[1][0]*A[2][2])/det;
        inv[1][1] = (A[0][0]*A[2][2]-A[0][2]*A[2][0])/det;
        inv[1][2] = (A[0][2]*A[1][0]-A[0][0]*A[1][2])/det;
        inv[2][0] = (A[1][0]*A[2][1]-A[1][1]*A[2][0])/det;
        inv[2][1] = (A[0][1]*A[2][0]-A[0][0]*A[2][1])/det;
        inv[2][2] = (A[0][0]*A[1][1]-A[0][1]*A[1][0])/det;
        for (int i = 0; i < 3; i++)
            for (int j = 0; j < 3; j++)
                C.m[i * 3 + j] = (float)inv[i][j];
        C.s = (float)(EP / (2.0 * (1.0 + VP)));
    }

    k_all<<<NB, QB>>>(new_xyz, xyz, gt_sdf, C, (float*)d_out);
}